// round 3
// baseline (speedup 1.0000x reference)
#include <cuda_runtime.h>
#include <math.h>

// Problem constants
#define NB    8
#define CC_   192
#define HH    112
#define WW    112
#define HW    (HH * WW)          // 12544
#define TILE  16
#define HALO  18
#define POS   (HALO * HALO)      // 324
#define FPOS  (17 * HALO)        // 306: rows 0..16 need forward dots
#define CCH   32
#define NCHUNK (CC_ / CCH)       // 6
#define INV_T 10.0f
#define NBLOCKS (7 * 7 * 8)      // 392
#define TOTAL_TERMS (8.0 * 8.0 * 112.0 * 112.0)

__device__ double   g_acc = 0.0;
__device__ unsigned g_cnt = 0u;

__global__ __launch_bounds__(256)
void dcl_kernel(const float* __restrict__ feat,
                const int*   __restrict__ labels,
                const int*   __restrict__ dirs,
                float*       __restrict__ out)
{
    __shared__ float s[CCH * POS];      // 41472 B, channel-major [c][pos]
    __shared__ float fdE_sh[FPOS];      // forward dots, accumulated over all C
    __shared__ float fdS_sh[FPOS];
    __shared__ float fdSE_sh[FPOS];
    __shared__ float fdSW_sh[FPOS];
    __shared__ float ssq_sh[POS];
    __shared__ float warpsum[8];

    const int n   = blockIdx.z;
    const int ti  = blockIdx.y * TILE;
    const int tj  = blockIdx.x * TILE;
    const int tid = threadIdx.x;
    const int li  = tid >> 4;
    const int lj  = tid & 15;
    const int gi  = ti + li;
    const int gj  = tj + lj;
    const int p0  = (li + 1) * HALO + (lj + 1);

    // ---- per-thread fixed position slots (computed once) ----
    // slot 1: p1 = tid (always < 306, so always does fd)
    const int p1   = tid;
    const int r1   = p1 / HALO;
    const int c1   = p1 - r1 * HALO;
    const int ii1  = ti - 1 + r1;
    const int jj1  = tj - 1 + c1;
    const bool ok1 = (ii1 >= 0) & (ii1 < HH) & (jj1 >= 0) & (jj1 < WW);
    const int go1  = ok1 ? (ii1 * WW + jj1) : 0;
    const bool eok1 = (c1 < 17);

    // slot 2: p2 = tid + 256 (load/ssq if tid < 68, fd if tid < 50)
    const int p2   = tid + 256;
    const bool has2 = (p2 < POS);
    const bool fd2  = (p2 < FPOS);
    const int r2   = p2 / HALO;
    const int c2   = p2 - r2 * HALO;
    const int ii2  = ti - 1 + r2;
    const int jj2  = tj - 1 + c2;
    const bool ok2 = has2 & (ii2 >= 0) & (ii2 < HH) & (jj2 >= 0) & (jj2 < WW);
    const int go2  = ok2 ? (ii2 * WW + jj2) : 0;
    const bool eok2 = (c2 < 17);

    // register accumulators (persist across channel chunks)
    float ss1 = 0.f, fdE1 = 0.f, fdS1 = 0.f, fdSE1 = 0.f, fdSW1 = 0.f;
    float ss2 = 0.f, fdE2 = 0.f, fdS2 = 0.f, fdSE2 = 0.f, fdSW2 = 0.f;

    const float* fbase = feat + (size_t)n * CC_ * HW;

    for (int ch = 0; ch < NCHUNK; ch++) {
        const float* fp = fbase + (size_t)ch * CCH * HW;
        __syncthreads();   // previous chunk's readers done

        // ---- load chunk: no divisions, independent LDGs ----
#pragma unroll 8
        for (int c = 0; c < CCH; c++) {
            float v1 = 0.f;
            if (ok1) v1 = __ldg(fp + c * HW + go1);
            s[c * POS + p1] = v1;
            if (has2) {
                float v2 = 0.f;
                if (ok2) v2 = __ldg(fp + c * HW + go2);
                s[c * POS + p2] = v2;
            }
        }
        __syncthreads();

        // ---- sumsq + 4 forward dots per owned position ----
#pragma unroll 8
        for (int c = 0; c < CCH; c++) {
            const float* sc = s + c * POS;
            {
                const float x = sc[p1];
                ss1 = fmaf(x, x, ss1);
                float vE  = eok1 ? sc[p1 + 1]        : 0.f;
                float vS  =        sc[p1 + HALO];
                float vSE = eok1 ? sc[p1 + HALO + 1] : 0.f;
                float vSW =        sc[p1 + HALO - 1];   // col0 value unused
                fdE1  = fmaf(x, vE,  fdE1);
                fdS1  = fmaf(x, vS,  fdS1);
                fdSE1 = fmaf(x, vSE, fdSE1);
                fdSW1 = fmaf(x, vSW, fdSW1);
            }
            if (has2) {
                const float x = sc[p2];
                ss2 = fmaf(x, x, ss2);
                if (fd2) {
                    float vE  = eok2 ? sc[p2 + 1]        : 0.f;
                    float vS  =        sc[p2 + HALO];
                    float vSE = eok2 ? sc[p2 + HALO + 1] : 0.f;
                    float vSW =        sc[p2 + HALO - 1];
                    fdE2  = fmaf(x, vE,  fdE2);
                    fdS2  = fmaf(x, vS,  fdS2);
                    fdSE2 = fmaf(x, vSE, fdSE2);
                    fdSW2 = fmaf(x, vSW, fdSW2);
                }
            }
        }
    }

    // ---- publish per-position results ----
    ssq_sh[p1] = ss1;
    fdE_sh[p1] = fdE1;  fdS_sh[p1] = fdS1;
    fdSE_sh[p1] = fdSE1; fdSW_sh[p1] = fdSW1;
    if (has2) ssq_sh[p2] = ss2;
    if (fd2) {
        fdE_sh[p2] = fdE2;  fdS_sh[p2] = fdS2;
        fdSE_sh[p2] = fdSE2; fdSW_sh[p2] = fdSW2;
    }
    __syncthreads();

    // ---- per-pixel loss over the 8 direction fields ----
    const float ssc  = ssq_sh[p0];
    const float invp = (ssc >= 1e-24f) ? rsqrtf(ssc) : 1e12f;

    float logits[8];
    int   maskv[8];
    float esum = 0.f;

#pragma unroll
    for (int m = 0; m < 8; m++) {
        const int d0 = __ldg(&dirs[((size_t)m * 2 + 0) * HW + gi * WW + gj]);
        const int d1 = __ldg(&dirs[((size_t)m * 2 + 1) * HW + gi * WW + gj]);
        const int pn = p0 + d0 * HALO + d1;        // neighbor position

        float draw;
        if (d0 == 0 && d1 == 0) {
            draw = ssc;                            // self dot == sumsq
        } else {
            const bool fwd = (d0 > 0) || (d0 == 0 && d1 > 0);
            const int  pq  = fwd ? p0 : pn;
            const int  a0  = fwd ? d0 : -d0;
            const int  a1  = fwd ? d1 : -d1;       // (0,1)(1,0)(1,1)(1,-1)
            const float* base = (a0 == 0) ? fdE_sh
                              : (a1 == 0) ? fdS_sh
                              : (a1 > 0)  ? fdSE_sh : fdSW_sh;
            draw = base[pq];
        }

        const float ssn  = ssq_sh[pn];
        const float invq = (ssn >= 1e-24f) ? rsqrtf(ssn) : 1e12f;
        const float logit = draw * invp * invq * INV_T;

        const int labm = __ldg(&labels[(size_t)m * HW + gi * WW + gj]);
        const int labg = __ldg(&labels[(size_t)n * HW + (gi + d0) * WW + (gj + d1)]);
        const int mk   = (labm == labg);

        logits[m] = logit;
        maskv[m]  = mk;
        esum += mk ? __expf(logit) : 0.f;
    }

    const float ld = __logf(esum + 1e-6f);
    float pix = 0.f;
#pragma unroll
    for (int m = 0; m < 8; m++)
        pix += maskv[m] ? (ld - logits[m]) : INFINITY;

    // ---- block reduction ----
    float v = pix;
#pragma unroll
    for (int off = 16; off > 0; off >>= 1)
        v += __shfl_xor_sync(0xffffffffu, v, off);
    if ((tid & 31) == 0) warpsum[tid >> 5] = v;
    __syncthreads();

    if (tid == 0) {
        double bs = 0.0;
#pragma unroll
        for (int w = 0; w < 8; w++) bs += (double)warpsum[w];
        atomicAdd(&g_acc, bs);
        __threadfence();
        const unsigned done = atomicAdd(&g_cnt, 1u);
        if (done == NBLOCKS - 1) {                 // last block finalizes
            // All 392 g_acc adds happened-before this point (each block:
            // g_acc add -> fence -> counter add; we observed all 392 counter
            // adds). Re-read g_acc atomically — do NOT trust our own stale
            // atomicAdd return value (that was the R2 bug: missed late adds).
            const double total = atomicAdd(&g_acc, 0.0);
            out[0] = (float)(total / TOTAL_TERMS);
            g_acc = 0.0;                           // reset for next replay
            g_cnt = 0u;
        }
    }
}

extern "C" void kernel_launch(void* const* d_in, const int* in_sizes, int n_in,
                              void* d_out, int out_size)
{
    const float* feat   = (const float*)d_in[0];
    const int*   labels = (const int*)  d_in[1];
    const int*   dirs   = (const int*)  d_in[2];
    float*       out    = (float*)d_out;

    dim3 grid(WW / TILE, HH / TILE, NB);   // (7, 7, 8)
    dcl_kernel<<<grid, 256>>>(feat, labels, dirs, out);
}